// round 4
// baseline (speedup 1.0000x reference)
#include <cuda_runtime.h>

#define Z 64      // z_dim
#define H 256     // hidden
#define C 5       // num classes
#define GMAX 16
#define MAXBLK 96

// partial class sums: layout [g][c][blk][d]
__device__ __align__(16) float g_part[GMAX * C * MAXBLK * Z];
__device__ int   g_cntp[MAXBLK * C];
__device__ __align__(16) float g_D[GMAX * C * Z];

__device__ __forceinline__ void acc_add(float4& a, const float4& v) {
    a.x += v.x; a.y += v.y; a.z += v.z; a.w += v.w;
}

// ------------------------------------------------------- per-class sum of x
// grid: (nblk, G+1). blockIdx.y == G -> label counting blocks.
// 256 threads = 16 groups of 16 lanes; lane = float4 chunk of dim, group strides nodes.
// 4-node unroll for MLP (4 independent LDG.128 in flight per thread).
__global__ void __launch_bounds__(256, 4)
reduce_kernel(const float* __restrict__ x,
              const int*   __restrict__ label,
              int N, int chunk, int nblk) {
    int g  = blockIdx.y;
    int bx = blockIdx.x;
    int n0 = bx * chunk;
    int n1 = min(n0 + chunk, N);
    int tid = threadIdx.x;

    if (g == (int)gridDim.y - 1) {
        // counting block: partial counts for this chunk
        int cnt[C];
#pragma unroll
        for (int c = 0; c < C; c++) cnt[c] = 0;
        for (int n = n0 + tid; n < n1; n += blockDim.x) {
            int c = __ldg(label + n);
#pragma unroll
            for (int cc = 0; cc < C; cc++) cnt[cc] += (cc == c);
        }
        __shared__ int scnt[C];
        if (tid < C) scnt[tid] = 0;
        __syncthreads();
#pragma unroll
        for (int cc = 0; cc < C; cc++)
            if (cnt[cc]) atomicAdd(&scnt[cc], cnt[cc]);
        __syncthreads();
        if (tid < C) g_cntp[bx * C + tid] = scnt[tid];
        return;
    }

    int lane = tid & 15;   // float4 index within 64-dim row
    int grp  = tid >> 4;   // 16 node-groups

    float4 acc[C];
#pragma unroll
    for (int c = 0; c < C; c++) acc[c] = make_float4(0.f, 0.f, 0.f, 0.f);

    const float4* x4 = reinterpret_cast<const float4*>(x) + (size_t)g * N * 16;

    int L = (n1 - n0) & ~63;        // nodes covered by the 4-unrolled loop
    int nEnd4 = n0 + L;
    int n = n0 + grp;
    for (; n < nEnd4; n += 64) {
        int    c0 = __ldg(label + n);
        int    c1 = __ldg(label + n + 16);
        int    c2 = __ldg(label + n + 32);
        int    c3 = __ldg(label + n + 48);
        float4 v0 = __ldg(x4 + (size_t)n * 16 + lane);
        float4 v1 = __ldg(x4 + (size_t)(n + 16) * 16 + lane);
        float4 v2 = __ldg(x4 + (size_t)(n + 32) * 16 + lane);
        float4 v3 = __ldg(x4 + (size_t)(n + 48) * 16 + lane);
#pragma unroll
        for (int cc = 0; cc < C; cc++) {
            if (c0 == cc) acc_add(acc[cc], v0);
            if (c1 == cc) acc_add(acc[cc], v1);
            if (c2 == cc) acc_add(acc[cc], v2);
            if (c3 == cc) acc_add(acc[cc], v3);
        }
    }
    for (; n < n1; n += 16) {
        int    c0 = __ldg(label + n);
        float4 v0 = __ldg(x4 + (size_t)n * 16 + lane);
#pragma unroll
        for (int cc = 0; cc < C; cc++)
            if (c0 == cc) acc_add(acc[cc], v0);
    }

    __shared__ float4 sacc[16][C][16];
#pragma unroll
    for (int c = 0; c < C; c++) sacc[grp][c][lane] = acc[c];
    __syncthreads();

    if (tid < C * 16) {
        int c = tid >> 4, d4 = tid & 15;
        float4 s = sacc[0][c][d4];
#pragma unroll
        for (int g2 = 1; g2 < 16; g2++) {
            float4 t = sacc[g2][c][d4];
            s.x += t.x; s.y += t.y; s.z += t.z; s.w += t.w;
        }
        float4* P4 = reinterpret_cast<float4*>(g_part);
        P4[((size_t)(g * C + c) * nblk + bx) * 16 + d4] = s;
    }
}

// ----------------------------------------- sum partials + tiny 2-layer GEMM
// block r = g*C + c computes D[r,:] = relu((S[r]/cnt) @ W1 + b1) @ W2 + b2
__global__ void mid_kernel(const float* __restrict__ W1,
                           const float* __restrict__ b1,
                           const float* __restrict__ W2,
                           const float* __restrict__ b2,
                           int nblk) {
    int r   = blockIdx.x;
    int g   = r / C;
    int c   = r % C;
    int tid = threadIdx.x;

    __shared__ int   scnt;
    __shared__ float s[Z];
    __shared__ float h[H];
    __shared__ float part[4][Z];

    if (tid == 0) scnt = 0;
    __syncthreads();
    if (tid < nblk) atomicAdd(&scnt, g_cntp[tid * C + c]);

    // sum partial class sums
    const float* P = g_part + (size_t)(g * C + c) * nblk * Z;
    int d = tid & 63, j = tid >> 6;
    float p = 0.f;
    for (int b = j; b < nblk; b += 4) p += P[b * Z + d];
    part[j][d] = p;
    __syncthreads();

    float inv = 1.f / (float)max(scnt, 1);
    if (tid < Z)
        s[tid] = (part[0][tid] + part[1][tid] + part[2][tid] + part[3][tid]) * inv;
    __syncthreads();

    // layer 1: h[j] = relu(sum_d s[d] * W1[d,j] + b1[j]), tid = j
    float acc = __ldg(b1 + tid);
#pragma unroll
    for (int dd = 0; dd < Z; dd++)
        acc = fmaf(s[dd], __ldg(W1 + dd * H + tid), acc);
    h[tid] = fmaxf(acc, 0.f);
    __syncthreads();

    // layer 2: D[k] = sum_j h[j] * W2[j,k] + b2[k]
    int lane = tid & 63, grp = tid >> 6;
    float p2 = 0.f;
#pragma unroll
    for (int jj = 0; jj < 64; jj++) {
        int jidx = grp * 64 + jj;
        p2 = fmaf(h[jidx], __ldg(W2 + jidx * Z + lane), p2);
    }
    __syncthreads();
    part[grp][lane] = p2;
    __syncthreads();
    if (tid < Z) {
        float dv = __ldg(b2 + tid) + part[0][tid] + part[1][tid]
                 + part[2][tid] + part[3][tid];
        g_D[r * Z + tid] = dv;
    }
}

// ------------------------------------ out[g,n,:] = x[g,n,:] + D[g,label[n],:]
// SAME (g, bx) chunking as reduce_kernel; each chunk is walked BACKWARD so the
// first touches hit the L2 residue its reduce twin left (chunk tail = last
// read). x loads are evict-first (__ldcs, no reuse); stores stream (__stcs)
// so output writes don't evict the x residue.
__global__ void __launch_bounds__(256, 6)
out_kernel(const float* __restrict__ x,
           const int*   __restrict__ label,
           float*       __restrict__ out,
           int N, int chunk) {
    int g  = blockIdx.y;
    int bx = blockIdx.x;

    __shared__ float4 sD[C * 16];
    if (threadIdx.x < C * 16)
        sD[threadIdx.x] =
            reinterpret_cast<const float4*>(g_D)[g * C * 16 + threadIdx.x];
    __syncthreads();

    int lane = threadIdx.x & 15;
    int grp  = threadIdx.x >> 4;
    int n0 = bx * chunk;
    int n1 = min(n0 + chunk, N);
    int iters = (n1 - n0 + 15) >> 4;

    const float4* x4 = reinterpret_cast<const float4*>(x);
    float4*       o4 = reinterpret_cast<float4*>(out);

#pragma unroll 4
    for (int i = iters - 1; i >= 0; i--) {
        int n = n0 + grp + (i << 4);
        if (n < n1) {
            int    c   = __ldg(label + n);
            size_t idx = ((size_t)g * N + n) * 16 + lane;
            float4 xv  = __ldcs(x4 + idx);
            float4 dv  = sD[c * 16 + lane];
            float4 rv;
            rv.x = xv.x + dv.x;
            rv.y = xv.y + dv.y;
            rv.z = xv.z + dv.z;
            rv.w = xv.w + dv.w;
            __stcs(o4 + idx, rv);
        }
    }
}

// ---------------------------------------------------------------- launcher
extern "C" void kernel_launch(void* const* d_in, const int* in_sizes, int n_in,
                              void* d_out, int out_size) {
    const float* x     = (const float*)d_in[0];
    const int*   label = (const int*)  d_in[1];
    const float* W1    = (const float*)d_in[2];
    const float* b1    = (const float*)d_in[3];
    const float* W2    = (const float*)d_in[4];
    const float* b2    = (const float*)d_in[5];
    float*       out   = (float*)d_out;

    int N = in_sizes[1];                 // 40000
    int G = in_sizes[0] / (N * Z);       // 16

    // Single balanced wave at 4 blocks/SM: (G+1)*nblk <= 592.
    // chunk multiple of 64 (clean 4-unroll).
    int chunk1 = 1216;
    int nblk = (N + chunk1 - 1) / chunk1;          // 33 for N=40000
    while ((G + 1) * nblk > 592 || nblk > MAXBLK) {
        chunk1 += 64;
        nblk = (N + chunk1 - 1) / chunk1;
    }

    dim3 grid1(nblk, G + 1);
    reduce_kernel<<<grid1, 256>>>(x, label, N, chunk1, nblk);

    mid_kernel<<<G * C, 256>>>(W1, b1, W2, b2, nblk);

    dim3 grid3(nblk, G);
    out_kernel<<<grid3, 256>>>(x, label, out, N, chunk1);
}

// round 5
// speedup vs baseline: 1.0781x; 1.0781x over previous
#include <cuda_runtime.h>

#define Z 64      // z_dim
#define H 256     // hidden
#define C 5       // num classes
#define GMAX 16
#define MAXBLK 96

// partial class sums: layout [g][c][blk][d]
__device__ __align__(16) float g_part[GMAX * C * MAXBLK * Z];
__device__ int   g_cntp[MAXBLK * C];
__device__ __align__(16) float g_D[GMAX * C * Z];

__device__ __forceinline__ void acc_add(float4& a, const float4& v) {
    a.x += v.x; a.y += v.y; a.z += v.z; a.w += v.w;
}

// ------------------------------------------------------- per-class sum of x
// grid: (nblk, G+1). blockIdx.y == G -> label counting blocks.
// 256 threads = 16 groups of 16 lanes; lane = float4 chunk of dim, group strides nodes.
// 6-node unroll: 6 independent LDG.128 in flight per thread -> 192 per SM at
// 4 blocks/SM, above the ~140 needed to hit the HBM roof at DRAM latency.
__global__ void __launch_bounds__(256, 4)
reduce_kernel(const float* __restrict__ x,
              const int*   __restrict__ label,
              int N, int chunk, int nblk) {
    int g  = blockIdx.y;
    int bx = blockIdx.x;
    int n0 = bx * chunk;
    int n1 = min(n0 + chunk, N);
    int tid = threadIdx.x;

    if (g == (int)gridDim.y - 1) {
        // counting block: partial counts for this chunk
        int cnt[C];
#pragma unroll
        for (int c = 0; c < C; c++) cnt[c] = 0;
        for (int n = n0 + tid; n < n1; n += blockDim.x) {
            int c = __ldg(label + n);
#pragma unroll
            for (int cc = 0; cc < C; cc++) cnt[cc] += (cc == c);
        }
        __shared__ int scnt[C];
        if (tid < C) scnt[tid] = 0;
        __syncthreads();
#pragma unroll
        for (int cc = 0; cc < C; cc++)
            if (cnt[cc]) atomicAdd(&scnt[cc], cnt[cc]);
        __syncthreads();
        if (tid < C) g_cntp[bx * C + tid] = scnt[tid];
        return;
    }

    int lane = tid & 15;   // float4 index within 64-dim row
    int grp  = tid >> 4;   // 16 node-groups

    float4 acc[C];
#pragma unroll
    for (int c = 0; c < C; c++) acc[c] = make_float4(0.f, 0.f, 0.f, 0.f);

    const float4* x4 = reinterpret_cast<const float4*>(x) + (size_t)g * N * 16;

    int span = n1 - n0;
    int L = span - span % 96;          // nodes covered by the 6-unrolled loop
    int nEnd6 = n0 + L;
    int n = n0 + grp;
    for (; n < nEnd6; n += 96) {
        int    c0 = __ldg(label + n);
        int    c1 = __ldg(label + n + 16);
        int    c2 = __ldg(label + n + 32);
        int    c3 = __ldg(label + n + 48);
        int    c4 = __ldg(label + n + 64);
        int    c5 = __ldg(label + n + 80);
        float4 v0 = __ldg(x4 + (size_t)n * 16 + lane);
        float4 v1 = __ldg(x4 + (size_t)(n + 16) * 16 + lane);
        float4 v2 = __ldg(x4 + (size_t)(n + 32) * 16 + lane);
        float4 v3 = __ldg(x4 + (size_t)(n + 48) * 16 + lane);
        float4 v4 = __ldg(x4 + (size_t)(n + 64) * 16 + lane);
        float4 v5 = __ldg(x4 + (size_t)(n + 80) * 16 + lane);
#pragma unroll
        for (int cc = 0; cc < C; cc++) {
            if (c0 == cc) acc_add(acc[cc], v0);
            if (c1 == cc) acc_add(acc[cc], v1);
            if (c2 == cc) acc_add(acc[cc], v2);
            if (c3 == cc) acc_add(acc[cc], v3);
            if (c4 == cc) acc_add(acc[cc], v4);
            if (c5 == cc) acc_add(acc[cc], v5);
        }
    }
    for (; n < n1; n += 16) {
        int    c0 = __ldg(label + n);
        float4 v0 = __ldg(x4 + (size_t)n * 16 + lane);
#pragma unroll
        for (int cc = 0; cc < C; cc++)
            if (c0 == cc) acc_add(acc[cc], v0);
    }

    __shared__ float4 sacc[16][C][16];
#pragma unroll
    for (int c = 0; c < C; c++) sacc[grp][c][lane] = acc[c];
    __syncthreads();

    if (tid < C * 16) {
        int c = tid >> 4, d4 = tid & 15;
        float4 s = sacc[0][c][d4];
#pragma unroll
        for (int g2 = 1; g2 < 16; g2++) {
            float4 t = sacc[g2][c][d4];
            s.x += t.x; s.y += t.y; s.z += t.z; s.w += t.w;
        }
        float4* P4 = reinterpret_cast<float4*>(g_part);
        P4[((size_t)(g * C + c) * nblk + bx) * 16 + d4] = s;
    }
}

// ----------------------------------------- sum partials + tiny 2-layer GEMM
// block r = g*C + c computes D[r,:] = relu((S[r]/cnt) @ W1 + b1) @ W2 + b2
__global__ void mid_kernel(const float* __restrict__ W1,
                           const float* __restrict__ b1,
                           const float* __restrict__ W2,
                           const float* __restrict__ b2,
                           int nblk) {
    int r   = blockIdx.x;
    int g   = r / C;
    int c   = r % C;
    int tid = threadIdx.x;

    __shared__ int   scnt;
    __shared__ float s[Z];
    __shared__ float h[H];
    __shared__ float part[4][Z];

    if (tid == 0) scnt = 0;
    __syncthreads();
    if (tid < nblk) atomicAdd(&scnt, g_cntp[tid * C + c]);

    // sum partial class sums
    const float* P = g_part + (size_t)(g * C + c) * nblk * Z;
    int d = tid & 63, j = tid >> 6;
    float p = 0.f;
    for (int b = j; b < nblk; b += 4) p += P[b * Z + d];
    part[j][d] = p;
    __syncthreads();

    float inv = 1.f / (float)max(scnt, 1);
    if (tid < Z)
        s[tid] = (part[0][tid] + part[1][tid] + part[2][tid] + part[3][tid]) * inv;
    __syncthreads();

    // layer 1: h[j] = relu(sum_d s[d] * W1[d,j] + b1[j]), tid = j
    float acc = __ldg(b1 + tid);
#pragma unroll
    for (int dd = 0; dd < Z; dd++)
        acc = fmaf(s[dd], __ldg(W1 + dd * H + tid), acc);
    h[tid] = fmaxf(acc, 0.f);
    __syncthreads();

    // layer 2: D[k] = sum_j h[j] * W2[j,k] + b2[k]
    int lane = tid & 63, grp = tid >> 6;
    float p2 = 0.f;
#pragma unroll
    for (int jj = 0; jj < 64; jj++) {
        int jidx = grp * 64 + jj;
        p2 = fmaf(h[jidx], __ldg(W2 + jidx * Z + lane), p2);
    }
    __syncthreads();
    part[grp][lane] = p2;
    __syncthreads();
    if (tid < Z) {
        float dv = __ldg(b2 + tid) + part[0][tid] + part[1][tid]
                 + part[2][tid] + part[3][tid];
        g_D[r * Z + tid] = dv;
    }
}

// ------------------------------------ out[g,n,:] = x[g,n,:] + D[g,label[n],:]
// R1 version (measured 48.3us @ 72.6% DRAM): forward walk, plain __ldg + store.
__global__ void out_kernel(const float* __restrict__ x,
                           const int*   __restrict__ label,
                           float*       __restrict__ out,
                           int N, int chunk) {
    int g = blockIdx.y;
    __shared__ float4 sD[C * 16];
    if (threadIdx.x < C * 16)
        sD[threadIdx.x] =
            reinterpret_cast<const float4*>(g_D)[g * C * 16 + threadIdx.x];
    __syncthreads();

    int lane = threadIdx.x & 15;
    int grp  = threadIdx.x >> 4;
    int n0 = blockIdx.x * chunk;
    int n1 = min(n0 + chunk, N);

    const float4* x4 = reinterpret_cast<const float4*>(x);
    float4*       o4 = reinterpret_cast<float4*>(out);

#pragma unroll 4
    for (int n = n0 + grp; n < n1; n += 16) {
        int    c   = __ldg(label + n);
        size_t idx = ((size_t)g * N + n) * 16 + lane;
        float4 xv  = __ldg(x4 + idx);
        float4 dv  = sD[c * 16 + lane];
        float4 rv;
        rv.x = xv.x + dv.x;
        rv.y = xv.y + dv.y;
        rv.z = xv.z + dv.z;
        rv.w = xv.w + dv.w;
        o4[idx] = rv;
    }
}

// ---------------------------------------------------------------- launcher
extern "C" void kernel_launch(void* const* d_in, const int* in_sizes, int n_in,
                              void* d_out, int out_size) {
    const float* x     = (const float*)d_in[0];
    const int*   label = (const int*)  d_in[1];
    const float* W1    = (const float*)d_in[2];
    const float* b1    = (const float*)d_in[3];
    const float* W2    = (const float*)d_in[4];
    const float* b2    = (const float*)d_in[5];
    float*       out   = (float*)d_out;

    int N = in_sizes[1];                 // 40000
    int G = in_sizes[0] / (N * Z);       // 16

    // Single balanced wave at 4 blocks/SM: (G+1)*nblk <= 592.
    // chunk multiple of 96 (clean 6-unroll).
    int chunk1 = 1248;
    int nblk = (N + chunk1 - 1) / chunk1;          // 33 for N=40000
    while ((G + 1) * nblk > 592 || nblk > MAXBLK) {
        chunk1 += 96;
        nblk = (N + chunk1 - 1) / chunk1;
    }

    dim3 grid1(nblk, G + 1);
    reduce_kernel<<<grid1, 256>>>(x, label, N, chunk1, nblk);

    mid_kernel<<<G * C, 256>>>(W1, b1, W2, b2, nblk);

    int chunk3 = 320;                    // multiple of 16
    dim3 grid3((N + chunk3 - 1) / chunk3, G);
    out_kernel<<<grid3, 256>>>(x, label, out, N, chunk3);
}

// round 6
// speedup vs baseline: 1.1046x; 1.0246x over previous
#include <cuda_runtime.h>

#define Z 64      // z_dim
#define H 256     // hidden
#define C 5       // num classes
#define GMAX 16
#define MAXBLK 64

// partial class sums: layout [g][c][blk][d]
__device__ __align__(16) float g_part[GMAX * C * MAXBLK * Z];
__device__ int      g_cnt[C];
__device__ __align__(16) float g_D[GMAX * C * Z];
__device__ unsigned g_bar1, g_bar2;

__global__ void init_kernel() {
    int t = threadIdx.x;
    if (t == 0) { g_bar1 = 0; g_bar2 = 0; }
    if (t < C) g_cnt[t] = 0;
}

__device__ __forceinline__ void acc_add(float4& a, const float4& v) {
    a.x += v.x; a.y += v.y; a.z += v.z; a.w += v.w;
}

// Persistent fused kernel. Grid (nblk, G), single wave (nblk*G <= 592 @ 4/SM).
// Phase 1: per-chunk class sums (+ label counts from g==0 row).
// Phase 2: tiny 2-layer GEMM in blocks bx < C.
// Phase 3: out = x + D[label], re-reading own chunk BACKWARD to hit L2 residue.
__global__ void __launch_bounds__(256, 4)
fused_kernel(const float* __restrict__ x,
             const int*   __restrict__ label,
             const float* __restrict__ W1,
             const float* __restrict__ b1,
             const float* __restrict__ W2,
             const float* __restrict__ b2,
             float*       __restrict__ out,
             int N, int chunk, int nblk, int total) {
    int g   = blockIdx.y;
    int bx  = blockIdx.x;
    int tid = threadIdx.x;
    int n0  = bx * chunk;
    int n1  = min(n0 + chunk, N);

    __shared__ float4 sacc[16][C][16];     // 20 KB
    __shared__ float  s_mid[Z];
    __shared__ float  h_mid[H];
    __shared__ float  part[4][Z];
    __shared__ int    scnt[C];
    __shared__ float4 sD[C * 16];

    // ---------------- phase 1a: label counting (g == 0 row only) ----------
    if (g == 0) {
        int cnt[C];
#pragma unroll
        for (int c = 0; c < C; c++) cnt[c] = 0;
        for (int n = n0 + tid; n < n1; n += 256) {
            int c = __ldg(label + n);
#pragma unroll
            for (int cc = 0; cc < C; cc++) cnt[cc] += (cc == c);
        }
        if (tid < C) scnt[tid] = 0;
        __syncthreads();
#pragma unroll
        for (int cc = 0; cc < C; cc++)
            if (cnt[cc]) atomicAdd(&scnt[cc], cnt[cc]);
        __syncthreads();
        if (tid < C) atomicAdd(&g_cnt[tid], scnt[tid]);
        __syncthreads();
    }

    // ---------------- phase 1b: per-class sum of own chunk ----------------
    {
        int lane = tid & 15;   // float4 index within 64-dim row
        int grp  = tid >> 4;   // 16 node-groups

        float4 acc[C];
#pragma unroll
        for (int c = 0; c < C; c++) acc[c] = make_float4(0.f, 0.f, 0.f, 0.f);

        const float4* x4 = reinterpret_cast<const float4*>(x) + (size_t)g * N * 16;

        int span  = n1 - n0;
        int nEnd6 = n0 + (span - span % 96);
        int n = n0 + grp;
        for (; n < nEnd6; n += 96) {
            int    c0 = __ldg(label + n);
            int    c1 = __ldg(label + n + 16);
            int    c2 = __ldg(label + n + 32);
            int    c3 = __ldg(label + n + 48);
            int    c4 = __ldg(label + n + 64);
            int    c5 = __ldg(label + n + 80);
            float4 v0 = __ldg(x4 + (size_t)n * 16 + lane);
            float4 v1 = __ldg(x4 + (size_t)(n + 16) * 16 + lane);
            float4 v2 = __ldg(x4 + (size_t)(n + 32) * 16 + lane);
            float4 v3 = __ldg(x4 + (size_t)(n + 48) * 16 + lane);
            float4 v4 = __ldg(x4 + (size_t)(n + 64) * 16 + lane);
            float4 v5 = __ldg(x4 + (size_t)(n + 80) * 16 + lane);
#pragma unroll
            for (int cc = 0; cc < C; cc++) {
                if (c0 == cc) acc_add(acc[cc], v0);
                if (c1 == cc) acc_add(acc[cc], v1);
                if (c2 == cc) acc_add(acc[cc], v2);
                if (c3 == cc) acc_add(acc[cc], v3);
                if (c4 == cc) acc_add(acc[cc], v4);
                if (c5 == cc) acc_add(acc[cc], v5);
            }
        }
        for (; n < n1; n += 16) {
            int    c0 = __ldg(label + n);
            float4 v0 = __ldg(x4 + (size_t)n * 16 + lane);
#pragma unroll
            for (int cc = 0; cc < C; cc++)
                if (c0 == cc) acc_add(acc[cc], v0);
        }

#pragma unroll
        for (int c = 0; c < C; c++) sacc[grp][c][lane] = acc[c];
        __syncthreads();

        if (tid < C * 16) {
            int c = tid >> 4, d4 = tid & 15;
            float4 s = sacc[0][c][d4];
#pragma unroll
            for (int g2 = 1; g2 < 16; g2++) {
                float4 t = sacc[g2][c][d4];
                s.x += t.x; s.y += t.y; s.z += t.z; s.w += t.w;
            }
            float4* P4 = reinterpret_cast<float4*>(g_part);
            P4[((size_t)(g * C + c) * nblk + bx) * 16 + d4] = s;
        }
    }

    // ---------------- grid barrier 1 --------------------------------------
    __syncthreads();
    if (tid == 0) {
        __threadfence();
        atomicAdd(&g_bar1, 1u);
        while (*(volatile unsigned*)&g_bar1 < (unsigned)total) { }
        __threadfence();
    }
    __syncthreads();

    // ---------------- phase 2: mid GEMM (blocks bx < C) -------------------
    if (bx < C) {
        int c = bx;
        int r = g * C + c;

        const float* P = g_part + (size_t)r * nblk * Z;
        int d = tid & 63, j = tid >> 6;
        float p = 0.f;
        for (int b = j; b < nblk; b += 4) p += P[b * Z + d];
        part[j][d] = p;
        __syncthreads();

        float inv = 1.f / (float)max(g_cnt[c], 1);
        if (tid < Z)
            s_mid[tid] = (part[0][tid] + part[1][tid] + part[2][tid] + part[3][tid]) * inv;
        __syncthreads();

        // layer 1
        float acc = __ldg(b1 + tid);
#pragma unroll
        for (int dd = 0; dd < Z; dd++)
            acc = fmaf(s_mid[dd], __ldg(W1 + dd * H + tid), acc);
        h_mid[tid] = fmaxf(acc, 0.f);
        __syncthreads();

        // layer 2
        int lane = tid & 63, grp = tid >> 6;
        float p2 = 0.f;
#pragma unroll
        for (int jj = 0; jj < 64; jj++) {
            int jidx = grp * 64 + jj;
            p2 = fmaf(h_mid[jidx], __ldg(W2 + jidx * Z + lane), p2);
        }
        __syncthreads();
        part[grp][lane] = p2;
        __syncthreads();
        if (tid < Z) {
            float dv = __ldg(b2 + tid) + part[0][tid] + part[1][tid]
                     + part[2][tid] + part[3][tid];
            g_D[r * Z + tid] = dv;
        }
    }

    // ---------------- grid barrier 2 --------------------------------------
    __syncthreads();
    if (tid == 0) {
        __threadfence();
        atomicAdd(&g_bar2, 1u);
        while (*(volatile unsigned*)&g_bar2 < (unsigned)total) { }
        __threadfence();
    }
    __syncthreads();

    // ---------------- phase 3: out = x + D[label], backward walk ----------
    if (tid < C * 16)
        sD[tid] = reinterpret_cast<const float4*>(g_D)[g * C * 16 + tid];
    __syncthreads();

    {
        int lane = tid & 15;
        int grp  = tid >> 4;
        int span = n1 - n0;
        int spanA = span & ~15;

        const float4* x4 = reinterpret_cast<const float4*>(x);
        float4*       o4 = reinterpret_cast<float4*>(out);

        // unaligned tail (top of chunk) first
        if (grp < (span & 15)) {
            int n = n0 + spanA + grp;
            int    c   = __ldg(label + n);
            size_t idx = ((size_t)g * N + n) * 16 + lane;
            float4 xv  = __ldg(x4 + idx);
            float4 dv  = sD[c * 16 + lane];
            float4 rv;
            rv.x = xv.x + dv.x; rv.y = xv.y + dv.y;
            rv.z = xv.z + dv.z; rv.w = xv.w + dv.w;
            __stcs(o4 + idx, rv);
        }

        // main: backward over aligned region — most-recently-read lines first
#pragma unroll 4
        for (int base = spanA - 16; base >= 0; base -= 16) {
            int n = n0 + base + grp;
            int    c   = __ldg(label + n);
            size_t idx = ((size_t)g * N + n) * 16 + lane;
            float4 xv  = __ldg(x4 + idx);
            float4 dv  = sD[c * 16 + lane];
            float4 rv;
            rv.x = xv.x + dv.x; rv.y = xv.y + dv.y;
            rv.z = xv.z + dv.z; rv.w = xv.w + dv.w;
            __stcs(o4 + idx, rv);
        }
    }
}

// ---------------------------------------------------------------- launcher
extern "C" void kernel_launch(void* const* d_in, const int* in_sizes, int n_in,
                              void* d_out, int out_size) {
    const float* x     = (const float*)d_in[0];
    const int*   label = (const int*)  d_in[1];
    const float* W1    = (const float*)d_in[2];
    const float* b1    = (const float*)d_in[3];
    const float* W2    = (const float*)d_in[4];
    const float* b2    = (const float*)d_in[5];
    float*       out   = (float*)d_out;

    int N = in_sizes[1];                 // 40000
    int G = in_sizes[0] / (N * Z);       // 16

    // Single wave with slack: blocks = G * nblk <= 576 (<592 slots @4/SM).
    int nblk = 576 / G;                  // 36 for G=16
    if (nblk > MAXBLK) nblk = MAXBLK;
    int chunk = ((N + nblk - 1) / nblk + 15) & ~15;   // multiple of 16
    nblk = (N + chunk - 1) / chunk;
    int total = nblk * G;

    init_kernel<<<1, 32>>>();

    dim3 grid(nblk, G);
    fused_kernel<<<grid, 256>>>(x, label, W1, b1, W2, b2, out,
                                N, chunk, nblk, total);
}